// round 4
// baseline (speedup 1.0000x reference)
#include <cuda_runtime.h>

#define BATCH 8
#define LBL 8
#define EDIM 4
#define HT 640
#define WD 640
#define HW (HT*WD)
#define NV4 (HW/4)
#define NTHR 256
#define WARPS 8
#define GX 128
#define NBLK_D (GX*BATCH)
#define DIAG 905.0966799187808f

typedef unsigned long long u64;
typedef unsigned int u32;

// ---------- scratch: ALL zero at rest (module load / post-finalize) ----------
__device__ u64   g_occ [BATCH][LBL];      // (max_key<<32)|second_key, key=~idx, 0=empty
__device__ float g_sumk[BATCH][LBL][EDIM];
__device__ float g_cntk[BATCH][LBL];
__device__ float g_cntf[BATCH][LBL];
__device__ float g_agg [BATCH][LBL];
__device__ float g_dr  [BATCH];           // rewritten before read each replay
__device__ u32   g_c2;
__device__ unsigned char g_lab[BATCH*HW];

// keep the two LARGEST keys at *p
__device__ __forceinline__ void merge_max2(u64* p, u32 k){
  u64 old = *p;
  for(;;){
    u32 g1 = (u32)(old>>32), g2 = (u32)old;
    if (k <= g2) return;
    u32 m1, m2;
    if (k > g1){ m1 = k; m2 = g1; } else { m1 = g1; m2 = k; }
    u64 nv = ((u64)m1<<32) | (u64)m2;
    u64 prev = atomicCAS(p, old, nv);
    if (prev == old) return;
    old = prev;
  }
}

// ---------------- pass A ----------------
__global__ void __launch_bounds__(NTHR) kA(const float* __restrict__ emb,
                                           const int*   __restrict__ inst,
                                           const float* __restrict__ kern,
                                           const float* __restrict__ tmask){
  const int b    = blockIdx.y;
  const int tid  = threadIdx.x;
  const int w    = tid >> 5;
  const int lane = tid & 31;
  __shared__ float s_sum[WARPS][LBL][EDIM][32];  // 32 KB
  __shared__ u32   s_cnt[WARPS][LBL][32];        //  8 KB (lo16=full, hi16=kern)
  __shared__ u64   s_occ[LBL];

  for (int i = tid; i < WARPS*LBL*EDIM*32; i += NTHR) ((float*)s_sum)[i] = 0.f;
  for (int i = tid; i < WARPS*LBL*32;      i += NTHR) ((u32*)  s_cnt)[i] = 0u;
  if (tid < LBL) s_occ[tid] = 0ull;
  __syncthreads();

  const float*  eb = emb + (size_t)b*EDIM*HW;
  const int4*   ip = (const int4*)  (inst  + (size_t)b*HW);
  const float4* kp = (const float4*)(kern  + (size_t)b*HW);
  const float4* tp = (const float4*)(tmask + (size_t)b*HW);
  uchar4*       lp = (uchar4*)(g_lab + (size_t)b*HW);

  float* mysum = &s_sum[w][0][0][lane];   // + l*128 + d*32
  u32*   mycnt = &s_cnt[w][0][lane];      // + l*32

  for (int i = blockIdx.x*NTHR + tid; i < NV4; i += GX*NTHR){
    int4   iv = ip[i];
    float4 kv = kp[i];
    float4 tv = tp[i];
    float4 e0 = ((const float4*)(eb       ))[i];
    float4 e1 = ((const float4*)(eb +  HW ))[i];
    float4 e2 = ((const float4*)(eb + 2*HW))[i];
    float4 e3 = ((const float4*)(eb + 3*HW))[i];

    int l0 = (tv.x > 0.5f) ? iv.x : 0;
    int l1 = (tv.y > 0.5f) ? iv.y : 0;
    int l2 = (tv.z > 0.5f) ? iv.z : 0;
    int l3 = (tv.w > 0.5f) ? iv.w : 0;
    lp[i] = make_uchar4((unsigned char)l0,(unsigned char)l1,
                        (unsigned char)l2,(unsigned char)l3);
    const int base = i*4;

#define PROC_A(LV, JJ, KF, E0, E1, E2, E3)                                   \
    if (LV > 0){                                                             \
      u32 key = ~(u32)(base+JJ);                                             \
      u32 lo  = ((volatile u32*)&s_occ[LV])[0];                              \
      if (key > lo) merge_max2(&s_occ[LV], key);                             \
      bool kf = (KF > 0.5f);                                                 \
      mycnt[LV*32] += kf ? 0x10001u : 1u;                                    \
      if (kf){                                                               \
        float* p = mysum + LV*(EDIM*32);                                     \
        p[0] += E0; p[32] += E1; p[64] += E2; p[96] += E3;                   \
      }                                                                      \
    }
    PROC_A(l0, 0, kv.x, e0.x, e1.x, e2.x, e3.x)
    PROC_A(l1, 1, kv.y, e0.y, e1.y, e2.y, e3.y)
    PROC_A(l2, 2, kv.z, e0.z, e1.z, e2.z, e3.z)
    PROC_A(l3, 3, kv.w, e0.w, e1.w, e2.w, e3.w)
#undef PROC_A
  }
  __syncthreads();

  if (tid < LBL){
    u64 v = s_occ[tid];
    if (v != 0ull){
      merge_max2(&g_occ[b][tid], (u32)(v>>32));
      u32 lo = (u32)v;
      if (lo) merge_max2(&g_occ[b][tid], lo);
    }
  }
  {
    int rw = tid>>5, rl = (tid>>2)&7, rd = tid&3;
    float s = 0.f;
    #pragma unroll
    for (int k = 0; k < 32; k++) s += s_sum[rw][rl][rd][(k+tid)&31];
    if (s != 0.f) atomicAdd(&g_sumk[b][rl][rd], s);
  }
  if (tid < 64){
    int rw = tid>>3, rl = tid&7;
    u32 c = 0u;
    #pragma unroll
    for (int k = 0; k < 32; k++) c += s_cnt[rw][rl][(k+tid)&31];
    if (c != 0u){
      float cf = (float)(c & 0xFFFFu);
      float ck = (float)(c >> 16);
      if (cf != 0.f) atomicAdd(&g_cntf[b][rl], cf);
      if (ck != 0.f) atomicAdd(&g_cntk[b][rl], ck);
    }
  }
}

// ---------------- pass D (+ small math, finalize, reset) ----------------
__global__ void __launch_bounds__(NTHR) kD(const float* __restrict__ emb,
                                           float* __restrict__ out){
  const int b    = blockIdx.y;
  const int tid  = threadIdx.x;
  const int w    = tid >> 5;
  const int lane = tid & 31;
  __shared__ float  s_val[WARPS][LBL][32];   // 8 KB
  __shared__ float4 sm4[LBL];
  __shared__ float  scd2[LBL], sss[LBL], sst[LBL];
  __shared__ float  red[64];
  __shared__ int    s_last;

  for (int i = tid; i < WARPS*LBL*32; i += NTHR) ((float*)s_val)[i] = 0.f;
  if (tid < LBL){
    float inv = 1.f / fmaxf(g_cntk[b][tid], 1.f);
    float4 m = make_float4(0.f,0.f,0.f,0.f);
    if (tid > 0){
      m.x = g_sumk[b][tid][0]*inv; m.y = g_sumk[b][tid][1]*inv;
      m.z = g_sumk[b][tid][2]*inv; m.w = g_sumk[b][tid][3]*inv;
    }
    sm4[tid] = m;
    u64 v  = g_occ[b][tid];
    u32 f  = ~(u32)(v>>32); if (f  > (u32)(HW-1)) f  = HW-1;
    u32 s2 = ~(u32)v;       if (s2 > (u32)(HW-1)) s2 = HW-1;
    float r0 = (float)(f  / WD), c0 = (float)(f  % WD);
    float r1 = (float)(s2 / WD), c1 = (float)(s2 % WD);
    float dx = r0 - c0, dy = r1 - c1;
    float cd = (tid > 0) ? __expf(__fsqrt_rn(dx*dx + dy*dy) * (0.5f/DIAG)) : 0.f;
    scd2[tid] = cd*cd;
    sss[tid] = r0 + c0;
    sst[tid] = r1 + c1;
  }
  __syncthreads();

  // block x==0 per image: l_dis + l_reg
  if (blockIdx.x == 0 && tid < 64){
    int ii = tid>>3, jj = tid&7;
    float acc = 0.f;
    if (ii != jj && ii > 0 && jj > 0){
      float4 a = sm4[ii], c = sm4[jj];
      float dx0=a.x-c.x, dx1=a.y-c.y, dx2=a.z-c.z, dx3=a.w-c.w;
      float Dn = __fsqrt_rn(dx0*dx0+dx1*dx1+dx2*dx2+dx3*dx3);
      float dsp = sss[ii]-sss[jj], dtp = sst[ii]-sst[jj];
      float dp  = __fsqrt_rn(dsp*dsp + dtp*dtp);
      float coef = 1.f - 20.f*__expf(-4.f - 2.5f*dp*(1.f/DIAG));
      float xx = fmaxf(3.f - coef*Dn, 0.f);
      acc = __logf(fmaf(xx,xx,1.f));
    }
    float reg = 0.f;
    if (tid < LBL){
      float4 a = sm4[tid];
      float sq = a.x*a.x + a.y*a.y + a.z*a.z + a.w*a.w;
      reg = __logf(__fsqrt_rn(sq) + 1.f);
    }
    red[tid] = acc*(1.f/42.f) + reg*(0.001f/8.f);
  }
  __syncthreads();
  if (blockIdx.x == 0 && tid < 32){
    float v = red[tid] + red[tid+32];
    #pragma unroll
    for (int o = 16; o > 0; o >>= 1) v += __shfl_down_sync(0xffffffffu, v, o);
    if (tid == 0) g_dr[b] = v;
  }

  const float*  eb = emb + (size_t)b*EDIM*HW;
  const uchar4* lp = (const uchar4*)(g_lab + (size_t)b*HW);
  float* myval = &s_val[w][0][lane];

  for (int i = blockIdx.x*NTHR + tid; i < NV4; i += GX*NTHR){
    uchar4 lv = lp[i];
    float4 e0 = ((const float4*)(eb       ))[i];
    float4 e1 = ((const float4*)(eb +  HW ))[i];
    float4 e2 = ((const float4*)(eb + 2*HW))[i];
    float4 e3 = ((const float4*)(eb + 3*HW))[i];

#define PROC_D(LV, E0, E1, E2, E3)                                           \
    if (LV > 0){                                                             \
      float4 m = sm4[LV];                                                    \
      float d0 = E0 - m.x, d1 = E1 - m.y, d2 = E2 - m.z, d3 = E3 - m.w;      \
      float sq = (d0*d0 + d1*d1 + d2*d2 + d3*d3) * scd2[LV];                 \
      float xx = fmaxf(__fsqrt_rn(sq) - 0.5f, 0.f);                          \
      myval[LV*32] += __logf(fmaf(xx,xx,1.f));                               \
    }
    { int l = lv.x; PROC_D(l, e0.x, e1.x, e2.x, e3.x) }
    { int l = lv.y; PROC_D(l, e0.y, e1.y, e2.y, e3.y) }
    { int l = lv.z; PROC_D(l, e0.z, e1.z, e2.z, e3.z) }
    { int l = lv.w; PROC_D(l, e0.w, e1.w, e2.w, e3.w) }
#undef PROC_D
  }
  __syncthreads();

  if (tid < 64){
    int rw = tid>>3, rl = tid&7;
    float sv = 0.f;
    #pragma unroll
    for (int k = 0; k < 32; k++) sv += s_val[rw][rl][(k+tid)&31];
    if (rl > 0 && sv != 0.f) atomicAdd(&g_agg[b][rl], sv);
  }
  __syncthreads();

  if (tid == 0){
    __threadfence();
    u32 old = atomicAdd(&g_c2, 1u);
    s_last = (old == (u32)(NBLK_D-1));
  }
  __syncthreads();
  if (!s_last) return;
  __threadfence();

  if (tid < BATCH){
    float s = 0.f;
    #pragma unroll
    for (int l = 1; l < LBL; l++)
      s += __ldcg(&g_agg[tid][l]) / fmaxf(__ldcg(&g_cntf[tid][l]), 1.f);
    red[tid] = s*(1.f/7.f) + __ldcg(&g_dr[tid]);
  }
  __syncthreads();
  if (tid == 0){
    float t = 0.f;
    #pragma unroll
    for (int i = 0; i < BATCH; i++) t += red[i];
    out[0] = t*(1.f/BATCH);
    g_c2 = 0u;
  }
  // reset scratch to zero-at-rest for next graph replay
  if (tid < BATCH*LBL*EDIM) ((float*)g_sumk)[tid] = 0.f;
  if (tid < BATCH*LBL){
    ((u64*)g_occ)[tid]    = 0ull;
    ((float*)g_cntk)[tid] = 0.f;
    ((float*)g_cntf)[tid] = 0.f;
    ((float*)g_agg )[tid] = 0.f;
  }
}

extern "C" void kernel_launch(void* const* d_in, const int* in_sizes, int n_in,
                              void* d_out, int out_size){
  const float* emb   = (const float*)d_in[0];
  const int*   inst  = (const int*)  d_in[1];
  const float* kern  = (const float*)d_in[2];
  const float* tmask = (const float*)d_in[3];
  // d_in[4] = bboxes, unused

  kA<<<dim3(GX, BATCH), NTHR>>>(emb, inst, kern, tmask);
  kD<<<dim3(GX, BATCH), NTHR>>>(emb, (float*)d_out);
}

// round 5
// speedup vs baseline: 1.6027x; 1.6027x over previous
#include <cuda_runtime.h>

#define BATCH 8
#define LBL 8
#define EDIM 4
#define HT 640
#define WD 640
#define HW (HT*WD)
#define NV4 (HW/4)
#define NTHR 256
#define WARPS 8
#define GX 92
#define NBLK_D (GX*BATCH)
#define DIAG 905.0966799187808f

typedef unsigned long long u64;
typedef unsigned int u32;

// ---------- scratch: ALL zero at rest (module load / post-finalize) ----------
__device__ u64   g_occ [BATCH][LBL];      // (max_key<<32)|second_key, key=~idx, 0=empty
__device__ float g_sumk[BATCH][LBL][EDIM];
__device__ float g_cntk[BATCH][LBL];
__device__ float g_cntf[BATCH][LBL];
__device__ float g_lagg[BATCH];           // weighted l_agg accumulator
__device__ float g_dr  [BATCH];           // rewritten before read each replay
__device__ u32   g_c2;
__device__ unsigned char g_lab[BATCH*HW];

// keep the two LARGEST keys at *p
__device__ __forceinline__ void merge_max2(u64* p, u32 k){
  u64 old = *p;
  for(;;){
    u32 g1 = (u32)(old>>32), g2 = (u32)old;
    if (k <= g2) return;
    u32 m1, m2;
    if (k > g1){ m1 = k; m2 = g1; } else { m1 = g1; m2 = k; }
    u64 nv = ((u64)m1<<32) | (u64)m2;
    u64 prev = atomicCAS(p, old, nv);
    if (prev == old) return;
    old = prev;
  }
}

// ---------------- pass A ----------------
__global__ void __launch_bounds__(NTHR) kA(const float* __restrict__ emb,
                                           const int*   __restrict__ inst,
                                           const float* __restrict__ kern,
                                           const float* __restrict__ tmask){
  const int b    = blockIdx.y;
  const int tid  = threadIdx.x;
  const int w    = tid >> 5;
  const int lane = tid & 31;
  __shared__ float4 s_sum[WARPS][LBL][32];  // 32 KB, per-lane float4
  __shared__ u32    s_cnt[WARPS][LBL][32];  //  8 KB (lo16=full, hi16=kern)
  __shared__ u64    s_occ[LBL];

  for (int i = tid; i < WARPS*LBL*32; i += NTHR){
    ((float4*)s_sum)[i] = make_float4(0.f,0.f,0.f,0.f);
    ((u32*)   s_cnt)[i] = 0u;
  }
  if (tid < LBL) s_occ[tid] = 0ull;
  __syncthreads();

  const float*  eb = emb + (size_t)b*EDIM*HW;
  const int4*   ip = (const int4*)  (inst  + (size_t)b*HW);
  const float4* kp = (const float4*)(kern  + (size_t)b*HW);
  const float4* tp = (const float4*)(tmask + (size_t)b*HW);
  uchar4*       lp = (uchar4*)(g_lab + (size_t)b*HW);

  float4* mysum = &s_sum[w][0][lane];   // + l*32 (float4 units)
  u32*    mycnt = &s_cnt[w][0][lane];   // + l*32

  for (int i = blockIdx.x*NTHR + tid; i < NV4; i += GX*NTHR){
    int4   iv = ip[i];
    float4 kv = kp[i];
    float4 tv = tp[i];
    float4 e0 = ((const float4*)(eb       ))[i];
    float4 e1 = ((const float4*)(eb +  HW ))[i];
    float4 e2 = ((const float4*)(eb + 2*HW))[i];
    float4 e3 = ((const float4*)(eb + 3*HW))[i];

    int l0 = (tv.x > 0.5f) ? iv.x : 0;
    int l1 = (tv.y > 0.5f) ? iv.y : 0;
    int l2 = (tv.z > 0.5f) ? iv.z : 0;
    int l3 = (tv.w > 0.5f) ? iv.w : 0;
    lp[i] = make_uchar4((unsigned char)l0,(unsigned char)l1,
                        (unsigned char)l2,(unsigned char)l3);
    const int base = i*4;

#define PROC_A(LV, JJ, KF, E0, E1, E2, E3)                                   \
    if (LV > 0){                                                             \
      u32 key = ~(u32)(base+JJ);                                             \
      u32 lo  = ((const u32*)&s_occ[LV])[0];                                 \
      if (key > lo) merge_max2(&s_occ[LV], key);                             \
      bool kf = (KF > 0.5f);                                                 \
      mycnt[LV*32] += kf ? 0x10001u : 1u;                                    \
      if (kf){                                                               \
        float4* p = mysum + LV*32;                                           \
        float4 v = *p;                                                       \
        v.x += E0; v.y += E1; v.z += E2; v.w += E3;                          \
        *p = v;                                                              \
      }                                                                      \
    }
    PROC_A(l0, 0, kv.x, e0.x, e1.x, e2.x, e3.x)
    PROC_A(l1, 1, kv.y, e0.y, e1.y, e2.y, e3.y)
    PROC_A(l2, 2, kv.z, e0.z, e1.z, e2.z, e3.z)
    PROC_A(l3, 3, kv.w, e0.w, e1.w, e2.w, e3.w)
#undef PROC_A
  }
  __syncthreads();

  if (tid < LBL){
    u64 v = s_occ[tid];
    if (v != 0ull){
      merge_max2(&g_occ[b][tid], (u32)(v>>32));
      u32 lo = (u32)v;
      if (lo) merge_max2(&g_occ[b][tid], lo);
    }
  }
  { // 256 threads: 8 groups of 32; group g handles label g, lane t sums 8 warps
    int rl = tid >> 5, rt = tid & 31;
    float4 s = make_float4(0.f,0.f,0.f,0.f);
    #pragma unroll
    for (int rw = 0; rw < WARPS; rw++){
      float4 v = s_sum[rw][rl][rt];
      s.x += v.x; s.y += v.y; s.z += v.z; s.w += v.w;
    }
    #pragma unroll
    for (int o = 16; o > 0; o >>= 1){
      s.x += __shfl_down_sync(0xffffffffu, s.x, o);
      s.y += __shfl_down_sync(0xffffffffu, s.y, o);
      s.z += __shfl_down_sync(0xffffffffu, s.z, o);
      s.w += __shfl_down_sync(0xffffffffu, s.w, o);
    }
    if (rt == 0 && rl > 0){
      if (s.x != 0.f) atomicAdd(&g_sumk[b][rl][0], s.x);
      if (s.y != 0.f) atomicAdd(&g_sumk[b][rl][1], s.y);
      if (s.z != 0.f) atomicAdd(&g_sumk[b][rl][2], s.z);
      if (s.w != 0.f) atomicAdd(&g_sumk[b][rl][3], s.w);
    }
  }
  if (tid < 64){
    int rw = tid>>3, rl = tid&7;
    u32 c = 0u;
    #pragma unroll
    for (int k = 0; k < 32; k++) c += s_cnt[rw][rl][(k+tid)&31];
    if (c != 0u){
      float cf = (float)(c & 0xFFFFu);
      float ck = (float)(c >> 16);
      if (cf != 0.f) atomicAdd(&g_cntf[b][rl], cf);
      if (ck != 0.f) atomicAdd(&g_cntk[b][rl], ck);
    }
  }
}

// ---------------- pass D (+ small math, finalize, reset) ----------------
__global__ void __launch_bounds__(NTHR) kD(const float* __restrict__ emb,
                                           float* __restrict__ out){
  const int b    = blockIdx.y;
  const int tid  = threadIdx.x;
  __shared__ float4 sm4[LBL];               // per-label kernel means
  __shared__ float2 scw[LBL];               // (cd^2, weight)
  __shared__ float  sss[LBL], sst[LBL];
  __shared__ float  red[64];
  __shared__ int    s_last;

  if (tid < LBL){
    float invk = 1.f / fmaxf(g_cntk[b][tid], 1.f);
    float4 m = make_float4(0.f,0.f,0.f,0.f);
    if (tid > 0){
      m.x = g_sumk[b][tid][0]*invk; m.y = g_sumk[b][tid][1]*invk;
      m.z = g_sumk[b][tid][2]*invk; m.w = g_sumk[b][tid][3]*invk;
    }
    sm4[tid] = m;
    u64 v  = g_occ[b][tid];
    u32 f  = ~(u32)(v>>32); if (f  > (u32)(HW-1)) f  = HW-1;
    u32 s2 = ~(u32)v;       if (s2 > (u32)(HW-1)) s2 = HW-1;
    float r0 = (float)(f  / WD), c0 = (float)(f  % WD);
    float r1 = (float)(s2 / WD), c1 = (float)(s2 % WD);
    float dx = r0 - c0, dy = r1 - c1;
    float cd = (tid > 0) ? __expf(__fsqrt_rn(dx*dx + dy*dy) * (0.5f/DIAG)) : 0.f;
    float wt = (tid > 0) ? 1.f / (7.f * fmaxf(g_cntf[b][tid], 1.f)) : 0.f;
    scw[tid] = make_float2(cd*cd, wt);
    sss[tid] = r0 + c0;
    sst[tid] = r1 + c1;
  }
  __syncthreads();

  // block x==0 per image: l_dis + l_reg
  if (blockIdx.x == 0 && tid < 64){
    int ii = tid>>3, jj = tid&7;
    float acc = 0.f;
    if (ii != jj && ii > 0 && jj > 0){
      float4 a = sm4[ii], c = sm4[jj];
      float dx0=a.x-c.x, dx1=a.y-c.y, dx2=a.z-c.z, dx3=a.w-c.w;
      float Dn = __fsqrt_rn(dx0*dx0+dx1*dx1+dx2*dx2+dx3*dx3);
      float dsp = sss[ii]-sss[jj], dtp = sst[ii]-sst[jj];
      float dp  = __fsqrt_rn(dsp*dsp + dtp*dtp);
      float coef = 1.f - 20.f*__expf(-4.f - 2.5f*dp*(1.f/DIAG));
      float xx = fmaxf(3.f - coef*Dn, 0.f);
      acc = __logf(fmaf(xx,xx,1.f));
    }
    float reg = 0.f;
    if (tid < LBL){
      float4 a = sm4[tid];
      float sq = a.x*a.x + a.y*a.y + a.z*a.z + a.w*a.w;
      reg = __logf(__fsqrt_rn(sq) + 1.f);
    }
    red[tid] = acc*(1.f/42.f) + reg*(0.001f/8.f);
  }
  __syncthreads();
  if (blockIdx.x == 0 && tid < 32){
    float v = red[tid] + red[tid+32];
    #pragma unroll
    for (int o = 16; o > 0; o >>= 1) v += __shfl_down_sync(0xffffffffu, v, o);
    if (tid == 0) g_dr[b] = v;
  }

  const float*  eb = emb + (size_t)b*EDIM*HW;
  const uchar4* lp = (const uchar4*)(g_lab + (size_t)b*HW);
  float acc = 0.f;   // register accumulator — no shared RMW in the loop

  for (int i = blockIdx.x*NTHR + tid; i < NV4; i += GX*NTHR){
    uchar4 lv = lp[i];
    float4 e0 = ((const float4*)(eb       ))[i];
    float4 e1 = ((const float4*)(eb +  HW ))[i];
    float4 e2 = ((const float4*)(eb + 2*HW))[i];
    float4 e3 = ((const float4*)(eb + 3*HW))[i];

#define PROC_D(LV, E0, E1, E2, E3)                                          \
    {                                                                        \
      float4 m = sm4[LV];                                                    \
      float2 cw = scw[LV];                                                   \
      float d0 = E0 - m.x, d1 = E1 - m.y, d2 = E2 - m.z, d3 = E3 - m.w;      \
      float sq = d0*d0 + d1*d1 + d2*d2 + d3*d3;                              \
      float t  = sq * cw.x;                                                  \
      float dist = t * __frsqrt_rn(fmaxf(t, 1e-30f));                        \
      float xx = fmaxf(dist - 0.5f, 0.f);                                    \
      acc = fmaf(__logf(fmaf(xx,xx,1.f)), cw.y, acc);                        \
    }
    { int l = lv.x; PROC_D(l, e0.x, e1.x, e2.x, e3.x) }
    { int l = lv.y; PROC_D(l, e0.y, e1.y, e2.y, e3.y) }
    { int l = lv.z; PROC_D(l, e0.z, e1.z, e2.z, e3.z) }
    { int l = lv.w; PROC_D(l, e0.w, e1.w, e2.w, e3.w) }
#undef PROC_D
  }

  // block reduction of acc
  #pragma unroll
  for (int o = 16; o > 0; o >>= 1) acc += __shfl_down_sync(0xffffffffu, acc, o);
  if ((tid & 31) == 0) red[tid>>5] = acc;
  __syncthreads();
  if (tid == 0){
    float t = 0.f;
    #pragma unroll
    for (int k = 0; k < WARPS; k++) t += red[k];
    atomicAdd(&g_lagg[b], t);
  }
  __syncthreads();

  if (tid == 0){
    __threadfence();
    u32 old = atomicAdd(&g_c2, 1u);
    s_last = (old == (u32)(NBLK_D-1));
  }
  __syncthreads();
  if (!s_last) return;
  __threadfence();

  if (tid < BATCH) red[tid] = __ldcg(&g_lagg[tid]) + __ldcg(&g_dr[tid]);
  __syncthreads();
  if (tid == 0){
    float t = 0.f;
    #pragma unroll
    for (int i = 0; i < BATCH; i++) t += red[i];
    out[0] = t*(1.f/BATCH);
    g_c2 = 0u;
  }
  // reset scratch to zero-at-rest for next graph replay
  if (tid < BATCH*LBL*EDIM) ((float*)g_sumk)[tid] = 0.f;
  if (tid < BATCH*LBL){
    ((u64*)g_occ)[tid]    = 0ull;
    ((float*)g_cntk)[tid] = 0.f;
    ((float*)g_cntf)[tid] = 0.f;
  }
  if (tid < BATCH) g_lagg[tid] = 0.f;
}

extern "C" void kernel_launch(void* const* d_in, const int* in_sizes, int n_in,
                              void* d_out, int out_size){
  const float* emb   = (const float*)d_in[0];
  const int*   inst  = (const int*)  d_in[1];
  const float* kern  = (const float*)d_in[2];
  const float* tmask = (const float*)d_in[3];
  // d_in[4] = bboxes, unused

  kA<<<dim3(GX, BATCH), NTHR>>>(emb, inst, kern, tmask);
  kD<<<dim3(GX, BATCH), NTHR>>>(emb, (float*)d_out);
}

// round 7
// speedup vs baseline: 2.3449x; 1.4632x over previous
#include <cuda_runtime.h>

#define BATCH 8
#define LBL 8
#define EDIM 4
#define HT 640
#define WD 640
#define HW (HT*WD)
#define NV4 (HW/4)
#define NTHR 256
#define WARPS 8
#define GX 92
#define NBLK_D (GX*BATCH)
#define DIAG 905.0966799187808f

typedef unsigned long long u64;
typedef unsigned int u32;

// ---------- scratch: ALL zero at rest (module load / post-finalize) ----------
__device__ u64   g_occ [BATCH][LBL];      // (max_key<<32)|second_key, key=~idx, 0=empty
__device__ float g_sumk[BATCH][LBL][EDIM];
__device__ float g_cntk[BATCH][LBL];
__device__ float g_cntf[BATCH][LBL];
__device__ float g_lagg[BATCH];
__device__ float g_dr  [BATCH];
__device__ u32   g_c2;
__device__ unsigned char g_lab[BATCH*HW];

// keep the two LARGEST keys at *p
__device__ __forceinline__ void merge_max2(u64* p, u32 k){
  u64 old = *p;
  for(;;){
    u32 g1 = (u32)(old>>32), g2 = (u32)old;
    if (k <= g2) return;
    u32 m1, m2;
    if (k > g1){ m1 = k; m2 = g1; } else { m1 = g1; m2 = k; }
    u64 nv = ((u64)m1<<32) | (u64)m2;
    u64 prev = atomicCAS(p, old, nv);
    if (prev == old) return;
    old = prev;
  }
}

// occurrence update for one subpixel; recompute threshold on the slow path
__device__ __forceinline__ void occ_update(int l, u32 key, u64* s_occ, u32* s_thr){
  if (l > 0){
    u32 lo = ((const u32*)&s_occ[l])[0];   // low word = second-best key
    if (key > lo){
      merge_max2(&s_occ[l], key);
      u32 t = 0xFFFFFFFFu;
      #pragma unroll
      for (int q = 1; q < LBL; q++){
        u32 v = ((const u32*)&s_occ[q])[0];
        t = (v < t) ? v : t;
      }
      *s_thr = t;
    }
  }
}

// ---------------- pass A ----------------
__global__ void __launch_bounds__(NTHR) kA(const float* __restrict__ emb,
                                           const int*   __restrict__ inst,
                                           const float* __restrict__ kern,
                                           const float* __restrict__ tmask){
  const int b    = blockIdx.y;
  const int tid  = threadIdx.x;
  const int w    = tid >> 5;
  const int lane = tid & 31;
  __shared__ float4 s_sum[WARPS][LBL][32];  // 32 KB
  __shared__ u64    s_occ[LBL];
  __shared__ u32    s_thr;                  // min over labels 1..7 of second key
  __shared__ u32    s_cntp[LBL];            // packed (cf | ck<<16)

  for (int i = tid; i < WARPS*LBL*32; i += NTHR)
    ((float4*)s_sum)[i] = make_float4(0.f,0.f,0.f,0.f);
  if (tid < LBL){ s_occ[tid] = 0ull; s_cntp[tid] = 0u; }
  if (tid == 0) s_thr = 0u;
  __syncthreads();

  const float*  eb = emb + (size_t)b*EDIM*HW;
  const int4*   ip = (const int4*)  (inst  + (size_t)b*HW);
  const float4* kp = (const float4*)(kern  + (size_t)b*HW);
  const float4* tp = (const float4*)(tmask + (size_t)b*HW);
  uchar4*       lp = (uchar4*)(g_lab + (size_t)b*HW);

  float4* mysum = &s_sum[w][0][lane];   // + l*32
  u64 cnt_full = 0ull, cnt_kern = 0ull; // 8x8-bit per-label counters (max 20 each)

  for (int i = blockIdx.x*NTHR + tid; i < NV4; i += GX*NTHR){
    int4   iv = ip[i];
    float4 kv = kp[i];
    float4 tv = tp[i];
    float4 e0 = ((const float4*)(eb       ))[i];
    float4 e1 = ((const float4*)(eb +  HW ))[i];
    float4 e2 = ((const float4*)(eb + 2*HW))[i];
    float4 e3 = ((const float4*)(eb + 3*HW))[i];

    int l0 = (tv.x > 0.5f) ? iv.x : 0;
    int l1 = (tv.y > 0.5f) ? iv.y : 0;
    int l2 = (tv.z > 0.5f) ? iv.z : 0;
    int l3 = (tv.w > 0.5f) ? iv.w : 0;
    lp[i] = make_uchar4((unsigned char)l0,(unsigned char)l1,
                        (unsigned char)l2,(unsigned char)l3);
    const int base = i*4;

    // quad-level occurrence guard: key of base+0 is the largest in the quad
    if (~(u32)base > s_thr){
      occ_update(l0, ~(u32)(base+0), s_occ, &s_thr);
      occ_update(l1, ~(u32)(base+1), s_occ, &s_thr);
      occ_update(l2, ~(u32)(base+2), s_occ, &s_thr);
      occ_update(l3, ~(u32)(base+3), s_occ, &s_thr);
    }

#define PROC_A(LV, KF, E0, E1, E2, E3)                                       \
    if (LV > 0){                                                             \
      u64 bit = 1ull << (LV*8);                                              \
      cnt_full += bit;                                                       \
      if (KF > 0.5f){                                                        \
        cnt_kern += bit;                                                     \
        float4* p = mysum + LV*32;                                           \
        float4 v = *p;                                                       \
        v.x += E0; v.y += E1; v.z += E2; v.w += E3;                          \
        *p = v;                                                              \
      }                                                                      \
    }
    PROC_A(l0, kv.x, e0.x, e1.x, e2.x, e3.x)
    PROC_A(l1, kv.y, e0.y, e1.y, e2.y, e3.y)
    PROC_A(l2, kv.z, e0.z, e1.z, e2.z, e3.z)
    PROC_A(l3, kv.w, e0.w, e1.w, e2.w, e3.w)
#undef PROC_A
  }

  // byte-wise warp reduction of counters: 3 xor rounds -> 8-lane partials (<=160)
  cnt_full += __shfl_xor_sync(0xffffffffu, cnt_full, 16);
  cnt_kern += __shfl_xor_sync(0xffffffffu, cnt_kern, 16);
  cnt_full += __shfl_xor_sync(0xffffffffu, cnt_full, 8);
  cnt_kern += __shfl_xor_sync(0xffffffffu, cnt_kern, 8);
  cnt_full += __shfl_xor_sync(0xffffffffu, cnt_full, 4);
  cnt_kern += __shfl_xor_sync(0xffffffffu, cnt_kern, 4);
  if (lane < 4){
    #pragma unroll
    for (int l = 1; l < LBL; l++){
      u32 cf = (u32)(cnt_full >> (l*8)) & 0xffu;
      u32 ck = (u32)(cnt_kern >> (l*8)) & 0xffu;
      u32 pk = cf | (ck << 16);
      if (pk) atomicAdd(&s_cntp[l], pk);
    }
  }
  __syncthreads();

  if (tid < LBL){
    u64 v = s_occ[tid];
    if (v != 0ull){
      merge_max2(&g_occ[b][tid], (u32)(v>>32));
      u32 lo = (u32)v;
      if (lo) merge_max2(&g_occ[b][tid], lo);
    }
    u32 c = s_cntp[tid];
    if (c){
      atomicAdd(&g_cntf[b][tid], (float)(c & 0xFFFFu));
      atomicAdd(&g_cntk[b][tid], (float)(c >> 16));
    }
  }
  { // label rl summed over 8 warps by 32 lanes, then warp-reduced
    int rl = tid >> 5, rt = tid & 31;
    float4 s = make_float4(0.f,0.f,0.f,0.f);
    #pragma unroll
    for (int rw = 0; rw < WARPS; rw++){
      float4 v = s_sum[rw][rl][rt];
      s.x += v.x; s.y += v.y; s.z += v.z; s.w += v.w;
    }
    #pragma unroll
    for (int o = 16; o > 0; o >>= 1){
      s.x += __shfl_down_sync(0xffffffffu, s.x, o);
      s.y += __shfl_down_sync(0xffffffffu, s.y, o);
      s.z += __shfl_down_sync(0xffffffffu, s.z, o);
      s.w += __shfl_down_sync(0xffffffffu, s.w, o);
    }
    if (rt == 0 && rl > 0){
      if (s.x != 0.f) atomicAdd(&g_sumk[b][rl][0], s.x);
      if (s.y != 0.f) atomicAdd(&g_sumk[b][rl][1], s.y);
      if (s.z != 0.f) atomicAdd(&g_sumk[b][rl][2], s.z);
      if (s.w != 0.f) atomicAdd(&g_sumk[b][rl][3], s.w);
    }
  }
}

// ---------------- pass D (+ small math, finalize, reset) ----------------
__global__ void __launch_bounds__(NTHR) kD(const float* __restrict__ emb,
                                           float* __restrict__ out){
  const int b    = blockIdx.y;
  const int tid  = threadIdx.x;
  __shared__ float4 sm4[LBL];
  __shared__ float2 scw[LBL];               // (cd^2, weight)
  __shared__ float  sss[LBL], sst[LBL];
  __shared__ float  red[64];
  __shared__ int    s_last;

  if (tid < LBL){
    float invk = 1.f / fmaxf(g_cntk[b][tid], 1.f);
    float4 m = make_float4(0.f,0.f,0.f,0.f);
    if (tid > 0){
      m.x = g_sumk[b][tid][0]*invk; m.y = g_sumk[b][tid][1]*invk;
      m.z = g_sumk[b][tid][2]*invk; m.w = g_sumk[b][tid][3]*invk;
    }
    sm4[tid] = m;
    u64 v  = g_occ[b][tid];
    u32 f  = ~(u32)(v>>32); if (f  > (u32)(HW-1)) f  = HW-1;
    u32 s2 = ~(u32)v;       if (s2 > (u32)(HW-1)) s2 = HW-1;
    float r0 = (float)(f  / WD), c0 = (float)(f  % WD);
    float r1 = (float)(s2 / WD), c1 = (float)(s2 % WD);
    float dx = r0 - c0, dy = r1 - c1;
    float cd = (tid > 0) ? __expf(__fsqrt_rn(dx*dx + dy*dy) * (0.5f/DIAG)) : 0.f;
    float wt = (tid > 0) ? 1.f / (7.f * fmaxf(g_cntf[b][tid], 1.f)) : 0.f;
    scw[tid] = make_float2(cd*cd, wt);
    sss[tid] = r0 + c0;
    sst[tid] = r1 + c1;
  }
  __syncthreads();

  if (blockIdx.x == 0 && tid < 64){
    int ii = tid>>3, jj = tid&7;
    float acc = 0.f;
    if (ii != jj && ii > 0 && jj > 0){
      float4 a = sm4[ii], c = sm4[jj];
      float dx0=a.x-c.x, dx1=a.y-c.y, dx2=a.z-c.z, dx3=a.w-c.w;
      float Dn = __fsqrt_rn(dx0*dx0+dx1*dx1+dx2*dx2+dx3*dx3);
      float dsp = sss[ii]-sss[jj], dtp = sst[ii]-sst[jj];
      float dp  = __fsqrt_rn(dsp*dsp + dtp*dtp);
      float coef = 1.f - 20.f*__expf(-4.f - 2.5f*dp*(1.f/DIAG));
      float xx = fmaxf(3.f - coef*Dn, 0.f);
      acc = __logf(fmaf(xx,xx,1.f));
    }
    float reg = 0.f;
    if (tid < LBL){
      float4 a = sm4[tid];
      float sq = a.x*a.x + a.y*a.y + a.z*a.z + a.w*a.w;
      reg = __logf(__fsqrt_rn(sq) + 1.f);
    }
    red[tid] = acc*(1.f/42.f) + reg*(0.001f/8.f);
  }
  __syncthreads();
  if (blockIdx.x == 0 && tid < 32){
    float v = red[tid] + red[tid+32];
    #pragma unroll
    for (int o = 16; o > 0; o >>= 1) v += __shfl_down_sync(0xffffffffu, v, o);
    if (tid == 0) g_dr[b] = v;
  }

  const float*  eb = emb + (size_t)b*EDIM*HW;
  const uchar4* lp = (const uchar4*)(g_lab + (size_t)b*HW);
  float acc = 0.f;

  for (int i = blockIdx.x*NTHR + tid; i < NV4; i += GX*NTHR){
    uchar4 lv = lp[i];
    float4 e0 = ((const float4*)(eb       ))[i];
    float4 e1 = ((const float4*)(eb +  HW ))[i];
    float4 e2 = ((const float4*)(eb + 2*HW))[i];
    float4 e3 = ((const float4*)(eb + 3*HW))[i];

#define PROC_D(LV, E0, E1, E2, E3)                                          \
    {                                                                        \
      float4 m = sm4[LV];                                                    \
      float2 cw = scw[LV];                                                   \
      float d0 = E0 - m.x, d1 = E1 - m.y, d2 = E2 - m.z, d3 = E3 - m.w;      \
      float sq = d0*d0 + d1*d1 + d2*d2 + d3*d3;                              \
      float t  = sq * cw.x;                                                  \
      float dist = t * __frsqrt_rn(fmaxf(t, 1e-30f));                        \
      float xx = fmaxf(dist - 0.5f, 0.f);                                    \
      acc = fmaf(__logf(fmaf(xx,xx,1.f)), cw.y, acc);                        \
    }
    { int l = lv.x; PROC_D(l, e0.x, e1.x, e2.x, e3.x) }
    { int l = lv.y; PROC_D(l, e0.y, e1.y, e2.y, e3.y) }
    { int l = lv.z; PROC_D(l, e0.z, e1.z, e2.z, e3.z) }
    { int l = lv.w; PROC_D(l, e0.w, e1.w, e2.w, e3.w) }
#undef PROC_D
  }

  #pragma unroll
  for (int o = 16; o > 0; o >>= 1) acc += __shfl_down_sync(0xffffffffu, acc, o);
  if ((tid & 31) == 0) red[tid>>5] = acc;
  __syncthreads();
  if (tid == 0){
    float t = 0.f;
    #pragma unroll
    for (int k = 0; k < WARPS; k++) t += red[k];
    atomicAdd(&g_lagg[b], t);
  }
  __syncthreads();

  if (tid == 0){
    __threadfence();
    u32 old = atomicAdd(&g_c2, 1u);
    s_last = (old == (u32)(NBLK_D-1));
  }
  __syncthreads();
  if (!s_last) return;
  __threadfence();

  if (tid < BATCH) red[tid] = __ldcg(&g_lagg[tid]) + __ldcg(&g_dr[tid]);
  __syncthreads();
  if (tid == 0){
    float t = 0.f;
    #pragma unroll
    for (int i = 0; i < BATCH; i++) t += red[i];
    out[0] = t*(1.f/BATCH);
    g_c2 = 0u;
  }
  if (tid < BATCH*LBL*EDIM) ((float*)g_sumk)[tid] = 0.f;
  if (tid < BATCH*LBL){
    ((u64*)g_occ)[tid]    = 0ull;
    ((float*)g_cntk)[tid] = 0.f;
    ((float*)g_cntf)[tid] = 0.f;
  }
  if (tid < BATCH) g_lagg[tid] = 0.f;
}

extern "C" void kernel_launch(void* const* d_in, const int* in_sizes, int n_in,
                              void* d_out, int out_size){
  const float* emb   = (const float*)d_in[0];
  const int*   inst  = (const int*)  d_in[1];
  const float* kern  = (const float*)d_in[2];
  const float* tmask = (const float*)d_in[3];
  // d_in[4] = bboxes, unused

  kA<<<dim3(GX, BATCH), NTHR>>>(emb, inst, kern, tmask);
  kD<<<dim3(GX, BATCH), NTHR>>>(emb, (float*)d_out);
}